// round 1
// baseline (speedup 1.0000x reference)
#include <cuda_runtime.h>
#include <math.h>

// BandPass biquad, 128 rows x 200000 samples.
// Chunked-parallel IIR: poles at radius ~0.831 => state decays 0.831^n,
// so each chunk of L samples is computed independently after W=128 warmup
// samples run with zero initial state (residual ~5e-11 relative).
// First chunk (c==0) uses the true zero initial condition exactly.

#define B_ROWS   128
#define T_LEN    200000
#define CHUNK_L  500          // 200000 / 500 = 400 chunks, divides exactly
#define WARM_W   128          // warmup samples (multiple of 4)
#define N_CHUNKS (T_LEN / CHUNK_L)

__global__ __launch_bounds__(128)
void biquad_chunk_kernel(const float* __restrict__ x,
                         float* __restrict__ y,
                         float b0, float b2, float na1, float na2)
{
    int gid = blockIdx.x * blockDim.x + threadIdx.x;
    int row = gid / N_CHUNKS;
    int c   = gid - row * N_CHUNKS;
    if (row >= B_ROWS) return;

    const float* xr = x + (size_t)row * T_LEN;
    float*       yr = y + (size_t)row * T_LEN;
    int s0 = c * CHUNK_L;

    float x1 = 0.0f, x2 = 0.0f, y1 = 0.0f, y2 = 0.0f;

    // One biquad step: y[n] = b0*x[n] + b2*x[n-2] - a1*y[n-1] - a2*y[n-2]
    // (b1 == 0 exactly in the reference)
#define BQ_STEP(XN, OUT_EXPR)                                               \
    do {                                                                    \
        float xn_ = (XN);                                                   \
        float yn_ = fmaf(b0, xn_, fmaf(b2, x2, fmaf(na1, y1, na2 * y2)));   \
        x2 = x1; x1 = xn_; y2 = y1; y1 = yn_;                               \
        OUT_EXPR;                                                           \
    } while (0)

    if (c > 0) {
        // Warmup: run [s0-W, s0) with zero state; result converges to true
        // state to within ~5e-11 relative by s0.
        const float4* wp = (const float4*)(xr + s0 - WARM_W);
#pragma unroll 8
        for (int i = 0; i < WARM_W / 4; ++i) {
            float4 v = wp[i];
            BQ_STEP(v.x, );
            BQ_STEP(v.y, );
            BQ_STEP(v.z, );
            BQ_STEP(v.w, );
        }
    }

    const float4* xp = (const float4*)(xr + s0);
    float4*       yp = (float4*)(yr + s0);
#pragma unroll 5
    for (int i = 0; i < CHUNK_L / 4; ++i) {
        float4 v = xp[i];
        float4 o;
        BQ_STEP(v.x, o.x = yn_);
        BQ_STEP(v.y, o.y = yn_);
        BQ_STEP(v.z, o.z = yn_);
        BQ_STEP(v.w, o.w = yn_);
        yp[i] = o;
    }
#undef BQ_STEP
}

extern "C" void kernel_launch(void* const* d_in, const int* in_sizes, int n_in,
                              void* d_out, int out_size)
{
    const float* x = (const float*)d_in[0];
    float*       y = (float*)d_out;

    // Coefficients computed in double, cast to float — mirrors the reference
    // (math.* in Python doubles, then jnp.float32).
    const double SR = 48000.0, CF = 2000.0, Q = 0.707;
    double w0    = 2.0 * M_PI * CF / SR;
    double alpha = sin(w0) / (2.0 * Q);
    double a0    = 1.0 + alpha;
    float b0  = (float)( alpha / a0);
    float b2  = (float)(-alpha / a0);
    float a1f = (float)((-2.0 * cos(w0)) / a0);
    float a2f = (float)((1.0 - alpha) / a0);
    float na1 = -a1f;
    float na2 = -a2f;

    int total   = B_ROWS * N_CHUNKS;          // 51200 threads
    int threads = 128;
    int blocks  = (total + threads - 1) / threads;  // 400
    biquad_chunk_kernel<<<blocks, threads>>>(x, y, b0, b2, na1, na2);
}